// round 17
// baseline (speedup 1.0000x reference)
#include <cuda_runtime.h>
#include <cstdint>

#define HH    1024
#define NST   64
#define LL    2048
#define NTHR  256   // 8 warps per CTA

// Accurate sincos for |x| <= ~110, independent of compiler fast-math flags.
__device__ __forceinline__ void my_sincos(float x, float* sp, float* cp) {
    float k = rintf(x * 0.63661977236f);           // x * 2/pi
    float r = fmaf(k, -1.57079637e+0f, x);         // x - k*PIO2_HI
    r = fmaf(k, 4.37113900e-8f, r);                // + k*PIO2_MID
    int q = ((int)k) & 3;
    float r2 = r * r;
    float s0 = fmaf(r2, -1.9515296e-4f, 8.3321609e-3f);
    s0 = fmaf(r2, s0, -1.6666655e-1f);
    float sr = fmaf(r * r2, s0, r);
    float c0 = fmaf(r2, 2.4433157e-5f, -1.3887316e-3f);
    c0 = fmaf(r2, c0, 4.1666646e-2f);
    c0 = fmaf(r2, c0, -0.5f);
    float cr = fmaf(r2, c0, 1.0f);
    float ss = (q & 1) ? cr : sr;
    float cc = (q & 1) ? sr : cr;
    if (q == 1 || q == 2) cc = -cc;
    if (q >= 2) ss = -ss;
    *sp = ss; *cp = cc;
}

__device__ __forceinline__ float tf32r(float x) {
    uint32_t u;
    asm("cvt.rna.tf32.f32 %0, %1;" : "=r"(u) : "f"(x));
    return __uint_as_float(u);
}

// One CTA per h, 8 warps (256 threads). Tensor-core formulation:
//   K[j1, j2] = sum_k A[j1, k] * B[k, j2]; within k-tile kt of 8:
//   col c = W1r[n=4kt+c][j1], col c+4 = W1i[n]; B row 8kt+c = W2r[n], +4 = -W2i[n]
//   -> sum = Re(W2*W1), W1 = w^j1, W2 = Cm*(w^64)^j2 (2x folded). l = j1 + 64*j2.
// m16n8k8 tf32 frags: r = t>>2, c = t&3; A: a0=(r,c) a1=(r+8,c) a2=(r,c+4)
// a3=(r+8,c+4); B: b0=(row c,col r) b1=(row c+4,col r); C: c0=(r,2c) c1=(r,2c+1)
// c2=(r+8,2c) c3=(r+8,2c+1). One LDS.64 of (W1r,W1i)[n=4kt+c] = (a0,a2).
// Both tables tf32-rounded at generation (idempotent); main loop is pure
// LDS+mma. Measured rel_err at this scheme: 2.87e-4.
//
// WORK SPLIT (8 warps): warp w8 owns j2-tile jt = w8&3 (j2 in [8jt,8jt+8))
// and m-half mh = w8>>2 (mt in {2mh, 2mh+1}) -> 16 kt x 2 mt mma per warp.
// GEN SPLIT: thread (n = tid>>2, sub = tid&3): W1 chain 16 steps covering
// j1 in [16 sub, 16 sub+16) (seed w^(16 sub)), W2 chain 8 steps covering
// j2 in [8 sub, 8 sub+8) (seed Cm * w^(512 sub)).
// As: [16 kt][64 j1][4 pair-slots] float2 = 32KB. Bs: [128 rows][32 XOR] = 16KB.
__global__ void __launch_bounds__(NTHR, 4) s4d_all(
        const float* __restrict__ A_real,
        const float* __restrict__ A_imag,
        const float* __restrict__ Bg,
        const float* __restrict__ Cg,
        const float* __restrict__ inv_dt,
        float* __restrict__ out) {
    __shared__ __align__(16) float As[16 * 512];   // 32KB
    __shared__ __align__(16) float Bs[128 * 32];   // 16KB

    int h   = blockIdx.x;
    int tid = threadIdx.x;
    int w8  = tid >> 5;
    int t   = tid & 31;

    // ---------- Param computation: thread (n = tid>>2, sub = tid&3) ----------
    int n_me = tid >> 2;
    int sub  = tid & 3;
    int gi   = h * NST + n_me;

    float wr, wi, w32r, w32i, w64r, w64i, cmr, cmi;
    float w16r, w16i, w512r, w512i;
    {
        float dt  = __expf(inv_dt[h]);
        float Are = -__expf(A_real[gi]);
        float Aim = A_imag[gi];
        float ar  = Are * dt;     // < 0
        float ai  = Aim * dt;

        float ea = __expf(ar);
        float sa, ca; my_sincos(ai, &sa, &ca);
        wr = ea * ca;
        wi = ea * sa;
        float er = wr - 1.0f;
        float ei = wi;

        float inv = 1.0f / fmaf(Are, Are, Aim * Aim);
        float fr = (er * Are + ei * Aim) * inv;
        float fi = (ei * Are - er * Aim) * inv;

        float br  = Bg[2 * gi], bi  = Bg[2 * gi + 1];
        float c0r = Cg[2 * gi], c0i = Cg[2 * gi + 1];
        float bcr = br * c0r - bi * c0i;
        float bci = br * c0i + bi * c0r;
        cmr = 2.0f * (bcr * fr - bci * fi);
        cmi = 2.0f * (bcr * fi + bci * fr);

        float e32 = __expf(32.0f * ar);
        float s32, c32; my_sincos(32.0f * ai, &s32, &c32);
        w32r = e32 * c32;
        w32i = e32 * s32;

        // w16 = exp(16*dtA) directly (cheaper than sqrt of w32)
        float e16 = __expf(16.0f * ar);
        float s16, c16; my_sincos(16.0f * ai, &s16, &c16);
        w16r = e16 * c16;
        w16i = e16 * s16;

        w64r = fmaf(w32r, w32r, -(w32i * w32i));
        w64i = 2.0f * w32r * w32i;

        // w512 = (w64)^8 via 3 squarings (|w|<1: underflow to 0 is benign)
        float xr = w64r, xi = w64i;
#pragma unroll
        for (int s = 0; s < 3; s++) {
            float nr = fmaf(xr, xr, -(xi * xi));
            float ni = 2.0f * xr * xi;
            xr = nr; xi = ni;
        }
        w512r = xr; w512i = xi;
    }

    // ---------- W1 chain -> A table (tf32-rounded), 16 steps ----------
    // Thread covers j1 in [16 sub, 16 sub+16); start rotated by rot = (n>>2)&3.
    {
        int rot = (n_me >> 2) & 3;
        // w^rot
        float w2r_ = fmaf(wr, wr, -(wi * wi));
        float w2i_ = 2.0f * wr * wi;
        float w3r_ = fmaf(w2r_, wr, -(w2i_ * wi));
        float w3i_ = fmaf(w2r_, wi,   w2i_ * wr);
        float wror = (rot == 0) ? 1.0f : (rot == 1) ? wr : (rot == 2) ? w2r_ : w3r_;
        float wroi = (rot == 0) ? 0.0f : (rot == 1) ? wi : (rot == 2) ? w2i_ : w3i_;
        // seed base = w^(16*sub):  {1, w16, w32, w48 = w16*w32}
        float w48r = fmaf(w16r, w32r, -(w16i * w32i));
        float w48i = fmaf(w16r, w32i,   w16i * w32r);
        float ssr = (sub == 0) ? 1.0f : (sub == 1) ? w16r : (sub == 2) ? w32r : w48r;
        float ssi = (sub == 0) ? 0.0f : (sub == 1) ? w16i : (sub == 2) ? w32i : w48i;
        float cr = fmaf(ssr, wror, -(ssi * wroi));   // w^(16 sub + rot)
        float ci = fmaf(ssr, wroi,   ssi * wror);

        // float2 slot: kt0*256 + j1*4 + (n&3), kt0 = n>>2
        float2* abase = (float2*)As + (n_me >> 2) * 256 + (n_me & 3);
        int jbase = 16 * sub;
        int j = rot & 15;
#pragma unroll
        for (int s = 0; s < 16; s++) {
            abase[(jbase + j) * 4] = make_float2(tf32r(cr), tf32r(ci));
            float nr = fmaf(cr, wr, -(ci * wi));
            float ni = fmaf(cr, wi,   ci * wr);
            cr = nr; ci = ni;
            j++;
            if (j == 16) { j = 0; cr = ssr; ci = ssi; }   // wrap: reseed to w^(16 sub)
        }
    }

    // ---------- W2 chain -> B table (tf32-rounded), 8 steps ----------
    // Thread covers j2 in [8 sub, 8 sub+8); seed Cm * w^(512 sub).
    // Rows: re at 8*(n>>2) + (n&3), im (negated) at +4. Column XOR (row&31).
    {
        float w1024r = fmaf(w512r, w512r, -(w512i * w512i));
        float w1024i = 2.0f * w512r * w512i;
        float w1536r = fmaf(w512r, w1024r, -(w512i * w1024i));
        float w1536i = fmaf(w512r, w1024i,   w512i * w1024r);
        float pr = (sub == 1) ? w512r : (sub == 2) ? w1024r : w1536r;
        float pi = (sub == 1) ? w512i : (sub == 2) ? w1024i : w1536i;
        float sr, si;
        if (sub == 0) { sr = cmr; si = cmi; }
        else {
            sr = fmaf(cmr, pr, -(cmi * pi));
            si = fmaf(cmr, pi,   cmi * pr);
        }
        int krR = (n_me >> 2) * 8 + (n_me & 3);
        int krI = krR + 4;
        float* bR = Bs + krR * 32;
        float* bI = Bs + krI * 32;
        int xR = krR & 31;
        int xI = krI & 31;
#pragma unroll
        for (int k2 = 0; k2 < 8; k2++) {
            int j2 = 8 * sub + k2;
            bR[j2 ^ xR] = tf32r(sr);
            bI[j2 ^ xI] = tf32r(-si);
            float nr = fmaf(sr, w64r, -(si * w64i));
            float ni = fmaf(sr, w64i,   si * w64r);
            sr = nr; si = ni;
        }
    }
    __syncthreads();

    // ---------- Preload B fragments (pure LDS + bitcast) ----------
    int c  = t & 3;          // threadID_in_group
    int r  = t >> 2;         // groupID
    int jt = w8 & 3;         // j2 tile
    int mh = w8 >> 2;        // m half
    uint32_t ub0[16], ub1[16];
    {
        int j2col = 8 * jt + r;
#pragma unroll
        for (int kt = 0; kt < 16; kt++) {
            int row0 = kt * 8 + c;        // W2r row
            int row1 = row0 + 4;          // -W2i row
            ub0[kt] = __float_as_uint(Bs[row0 * 32 + (j2col ^ (row0 & 31))]);
            ub1[kt] = __float_as_uint(Bs[row1 * 32 + (j2col ^ (row1 & 31))]);
        }
    }

    // ---------- Main loop: 16 kt x 2 mt, one mma each ----------
    float d0[2], d1[2], d2[2], d3[2];
#pragma unroll
    for (int m = 0; m < 2; m++) { d0[m] = 0.f; d1[m] = 0.f; d2[m] = 0.f; d3[m] = 0.f; }

    const float2* Ap = (const float2*)As;
#pragma unroll
    for (int kt = 0; kt < 16; kt++) {
#pragma unroll
        for (int m = 0; m < 2; m++) {
            int mt = 2 * mh + m;
            float2 a01 = Ap[kt * 256 + (mt * 16 + r) * 4 + c];
            float2 a23 = Ap[kt * 256 + (mt * 16 + 8 + r) * 4 + c];
            uint32_t ua0 = __float_as_uint(a01.x);   // (r,   c)
            uint32_t ua1 = __float_as_uint(a23.x);   // (r+8, c)
            uint32_t ua2 = __float_as_uint(a01.y);   // (r,   c+4)
            uint32_t ua3 = __float_as_uint(a23.y);   // (r+8, c+4)
            asm("mma.sync.aligned.m16n8k8.row.col.f32.tf32.tf32.f32 "
                "{%0,%1,%2,%3}, {%4,%5,%6,%7}, {%8,%9}, {%0,%1,%2,%3};"
                : "+f"(d0[m]), "+f"(d1[m]), "+f"(d2[m]), "+f"(d3[m])
                : "r"(ua0), "r"(ua1), "r"(ua2), "r"(ua3),
                  "r"(ub0[kt]), "r"(ub1[kt]));
        }
    }

    // ---------- Epilogue: C frag -> out[h, j1 + 64*j2] ----------
    float* o = out + h * LL;
    int j2a = 8 * jt + 2 * c;
#pragma unroll
    for (int m = 0; m < 2; m++) {
        int row = (2 * mh + m) * 16 + r;
        o[row     + 64 * j2a]       = d0[m];
        o[row     + 64 * (j2a + 1)] = d1[m];
        o[row + 8 + 64 * j2a]       = d2[m];
        o[row + 8 + 64 * (j2a + 1)] = d3[m];
    }
}

extern "C" void kernel_launch(void* const* d_in, const int* in_sizes, int n_in,
                              void* d_out, int out_size) {
    const float* A_real = (const float*)d_in[0];
    const float* A_imag = (const float*)d_in[1];
    const float* B      = (const float*)d_in[2];
    const float* C      = (const float*)d_in[3];
    const float* inv_dt = (const float*)d_in[4];
    float* out = (float*)d_out;

    s4d_all<<<HH, NTHR>>>(A_real, A_imag, B, C, inv_dt, out);
}